// round 2
// baseline (speedup 1.0000x reference)
#include <cuda_runtime.h>
#include <math.h>

#define Bn 256
#define Tn 128
#define En 300
#define Hn 512
#define G4 2048   // 4*H
#define KKn 812   // E+H

// ---------------- scratch (static device globals; no allocation) ----------------
__device__ float g_h[4 * Bn * Hn];         // hidden state per lstm  [l][b][j]
__device__ float g_c[4 * Bn * Hn];         // cell state
__device__ float g_gates[4 * Bn * G4];     // per-step gate pre-activations
__device__ float g_rnn[Bn * G4];           // concat cell states [256, 2048]
__device__ float g_bufA[Bn * 1024];
__device__ float g_bufB[Bn * 1024];

__device__ __forceinline__ float sigf(float x) { return 1.f / (1.f + expf(-x)); }

// =====================================================================
// Fused LSTM step GEMM:  gates[l] = [x_t(l), h(l)] @ W(l) + b(l)
// M=256 per lstm (blockIdx.z = lstm), N=2048, K=812
// 128x128 tile, 256 threads, 8x8 per thread (split 4+4), double-buffered.
// =====================================================================
__global__ __launch_bounds__(256) void lstm_step_gemm(
    const float* __restrict__ prem, const float* __restrict__ hyp,
    const float* __restrict__ W0, const float* __restrict__ W1,
    const float* __restrict__ W2, const float* __restrict__ W3,
    const float* __restrict__ b0, const float* __restrict__ b1,
    const float* __restrict__ b2, const float* __restrict__ b3,
    int t)
{
    const int l = blockIdx.z;
    const float* X    = (l < 2) ? prem : hyp;
    const float* W    = (l == 0) ? W0 : (l == 1) ? W1 : (l == 2) ? W2 : W3;
    const float* bias = (l == 0) ? b0 : (l == 1) ? b1 : (l == 2) ? b2 : b3;
    const int tt = (l & 1) ? (Tn - 1 - t) : t;   // bw lstms read reversed time
    const float* __restrict__ hp = g_h + (size_t)l * Bn * Hn;

    __shared__ __align__(16) float As[2][8][132];   // stride 132: conflict-free writes
    __shared__ __align__(16) float Ws[2][8][132];

    const int tid = threadIdx.x;
    const int tx = tid & 15, ty = tid >> 4;
    const int row0 = blockIdx.y * 128;
    const int col0 = blockIdx.x * 128;

    float acc[8][8];
#pragma unroll
    for (int i = 0; i < 8; i++)
#pragma unroll
        for (int j = 0; j < 8; j++) acc[i][j] = 0.f;

    const int NT = (KKn + 7) / 8;   // 102 k-tiles

    auto loadA = [&](int k0, int it) -> float {
        int idx = it * 256 + tid;
        int kk = idx & 7, ar = idx >> 3;
        int kg = k0 + kk;
        int b = row0 + ar;
        if (kg < En)        return X[(b * Tn + tt) * En + kg];
        else if (kg < KKn)  return hp[b * Hn + (kg - En)];
        else                return 0.f;
    };
    auto loadW = [&](int k0, int it) -> float {
        int idx = it * 256 + tid;
        int wc = idx & 127, wk = idx >> 7;
        int kg = k0 + wk;
        return (kg < KKn) ? W[(size_t)kg * G4 + col0 + wc] : 0.f;
    };

    // preload tile 0
#pragma unroll
    for (int it = 0; it < 4; it++) {
        int idx = it * 256 + tid;
        As[0][idx & 7][idx >> 3]    = loadA(0, it);
        Ws[0][idx >> 7][idx & 127]  = loadW(0, it);
    }
    __syncthreads();

    for (int kt = 0; kt < NT; kt++) {
        float pa[4], pw[4];
        if (kt + 1 < NT) {
#pragma unroll
            for (int it = 0; it < 4; it++) {
                pa[it] = loadA((kt + 1) * 8, it);
                pw[it] = loadW((kt + 1) * 8, it);
            }
        }
        const int buf = kt & 1;
#pragma unroll
        for (int kk = 0; kk < 8; kk++) {
            // split 4+4 to keep LDS.128 phases conflict-free
            float4 a0 = *(const float4*)&As[buf][kk][ty * 4];
            float4 a1 = *(const float4*)&As[buf][kk][64 + ty * 4];
            float4 w0 = *(const float4*)&Ws[buf][kk][tx * 4];
            float4 w1 = *(const float4*)&Ws[buf][kk][64 + tx * 4];
            float ra[8] = {a0.x, a0.y, a0.z, a0.w, a1.x, a1.y, a1.z, a1.w};
            float rw[8] = {w0.x, w0.y, w0.z, w0.w, w1.x, w1.y, w1.z, w1.w};
#pragma unroll
            for (int i = 0; i < 8; i++)
#pragma unroll
                for (int j = 0; j < 8; j++) acc[i][j] += ra[i] * rw[j];
        }
        if (kt + 1 < NT) {
            const int nb = buf ^ 1;
#pragma unroll
            for (int it = 0; it < 4; it++) {
                int idx = it * 256 + tid;
                As[nb][idx & 7][idx >> 3]   = pa[it];
                Ws[nb][idx >> 7][idx & 127] = pw[it];
            }
            __syncthreads();
        }
    }

    float* __restrict__ gout = g_gates + (size_t)l * Bn * G4;
#pragma unroll
    for (int i = 0; i < 8; i++) {
        int row = row0 + ((i < 4) ? (ty * 4 + i) : (64 + ty * 4 + (i - 4)));
#pragma unroll
        for (int jh = 0; jh < 2; jh++) {
            int col = col0 + ((jh == 0) ? (tx * 4) : (64 + tx * 4));
            float4 v;
            v.x = acc[i][jh * 4 + 0] + bias[col + 0];
            v.y = acc[i][jh * 4 + 1] + bias[col + 1];
            v.z = acc[i][jh * 4 + 2] + bias[col + 2];
            v.w = acc[i][jh * 4 + 3] + bias[col + 3];
            *(float4*)&gout[(size_t)row * G4 + col] = v;
        }
    }
}

// ---------------- elementwise LSTM state update (float4 vectorized) ----------------
__global__ void lstm_update()
{
    int v = blockIdx.x * blockDim.x + threadIdx.x;   // vec4 index
    if (v >= 4 * Bn * Hn / 4) return;
    int idx = v * 4;
    int lb = idx / Hn;     // l*256 + b
    int j  = idx - lb * Hn;
    const float* __restrict__ g = g_gates + (size_t)lb * G4;
    float4 gi = *(const float4*)&g[j];
    float4 gj = *(const float4*)&g[Hn + j];
    float4 gf = *(const float4*)&g[2 * Hn + j];
    float4 go = *(const float4*)&g[3 * Hn + j];
    float4 cc = *(const float4*)&g_c[idx];
    float4 cn, hn;
    cn.x = cc.x * sigf(gf.x + 1.f) + sigf(gi.x) * tanhf(gj.x);
    cn.y = cc.y * sigf(gf.y + 1.f) + sigf(gi.y) * tanhf(gj.y);
    cn.z = cc.z * sigf(gf.z + 1.f) + sigf(gi.z) * tanhf(gj.z);
    cn.w = cc.w * sigf(gf.w + 1.f) + sigf(gi.w) * tanhf(gj.w);
    hn.x = tanhf(cn.x) * sigf(go.x);
    hn.y = tanhf(cn.y) * sigf(go.y);
    hn.z = tanhf(cn.z) * sigf(go.z);
    hn.w = tanhf(cn.w) * sigf(go.w);
    *(float4*)&g_c[idx] = cn;
    *(float4*)&g_h[idx] = hn;
}

__global__ void zero_hc()
{
    int i = blockIdx.x * blockDim.x + threadIdx.x;
    if (i < 4 * Bn * Hn) { g_h[i] = 0.f; g_c[i] = 0.f; }
}

// rnn_out[b, l*512 + j] = c[l][b][j]
__global__ void build_rnn()
{
    int idx = blockIdx.x * blockDim.x + threadIdx.x;
    if (idx >= 4 * Bn * Hn) return;
    int l = idx / (Bn * Hn);
    int r = idx - l * Bn * Hn;
    int b = r / Hn, j = r - b * Hn;
    g_rnn[b * G4 + l * Hn + j] = g_c[idx];
}

// ---------------- MLP GEMM: 64x64 tile, 256 threads, 4x4 per thread ----------------
// asel/csel select static device buffers (host can't take their address).
__global__ __launch_bounds__(256) void mlp_gemm(
    int asel, const float* __restrict__ W, const float* __restrict__ bias,
    int csel, int M, int N, int K, int act)
{
    const float* __restrict__ A = (asel == 0) ? g_rnn : (asel == 1) ? g_bufA : g_bufB;
    float* __restrict__ C = (csel == 1) ? g_bufA : g_bufB;

    __shared__ __align__(16) float As[16][68];
    __shared__ __align__(16) float Ws[16][68];
    int tid = threadIdx.x, tx = tid & 15, ty = tid >> 4;
    int row0 = blockIdx.y * 64, col0 = blockIdx.x * 64;
    float acc[4][4] = {};

    for (int k0 = 0; k0 < K; k0 += 16) {
#pragma unroll
        for (int it = 0; it < 4; it++) {
            int idx = it * 256 + tid;
            int kk = idx & 15, ar = idx >> 4;
            As[kk][ar] = A[(size_t)(row0 + ar) * K + k0 + kk];
            int wc = idx & 63, wk = idx >> 6;
            Ws[wk][wc] = W[(size_t)(k0 + wk) * N + col0 + wc];
        }
        __syncthreads();
#pragma unroll
        for (int kk = 0; kk < 16; kk++) {
            float4 ra = *(const float4*)&As[kk][ty * 4];
            float4 rw = *(const float4*)&Ws[kk][tx * 4];
            float a[4] = {ra.x, ra.y, ra.z, ra.w};
            float w[4] = {rw.x, rw.y, rw.z, rw.w};
#pragma unroll
            for (int i = 0; i < 4; i++)
#pragma unroll
                for (int j = 0; j < 4; j++) acc[i][j] += a[i] * w[j];
        }
        __syncthreads();
    }
#pragma unroll
    for (int i = 0; i < 4; i++) {
        int row = row0 + ty * 4 + i;
#pragma unroll
        for (int j = 0; j < 4; j++) {
            int col = col0 + tx * 4 + j;
            float v = acc[i][j] + bias[col];
            if (act) v = tanhf(v);
            C[(size_t)row * N + col] = v;
        }
    }
}

// ---------------- final [256,1024] @ [1024,3] + b4 ----------------
__global__ void final_gemm(const float* __restrict__ W4, const float* __restrict__ b4,
                           float* __restrict__ out)
{
    int b = blockIdx.x;
    int tid = threadIdx.x;   // 128
    float s0 = 0.f, s1 = 0.f, s2 = 0.f;
    const float* __restrict__ A = g_bufA + (size_t)b * 1024;
    for (int k = tid; k < 1024; k += 128) {
        float a = A[k];
        s0 += a * W4[k * 3 + 0];
        s1 += a * W4[k * 3 + 1];
        s2 += a * W4[k * 3 + 2];
    }
    // warp-level reduce, then cross-warp via smem
    for (int off = 16; off > 0; off >>= 1) {
        s0 += __shfl_down_sync(0xffffffffu, s0, off);
        s1 += __shfl_down_sync(0xffffffffu, s1, off);
        s2 += __shfl_down_sync(0xffffffffu, s2, off);
    }
    __shared__ float sh[3][4];
    int w = tid >> 5;
    if ((tid & 31) == 0) { sh[0][w] = s0; sh[1][w] = s1; sh[2][w] = s2; }
    __syncthreads();
    if (tid < 3) {
        float v = sh[tid][0] + sh[tid][1] + sh[tid][2] + sh[tid][3];
        out[b * 3 + tid] = v + b4[tid];
    }
}

// =====================================================================
extern "C" void kernel_launch(void* const* d_in, const int* in_sizes, int n_in,
                              void* d_out, int out_size)
{
    const float* prem = (const float*)d_in[0];
    const float* hyp  = (const float*)d_in[1];
    // lstm order: 0 = fw_p, 1 = bw_p, 2 = fw_h, 3 = bw_h (matches rnn_out concat order)
    const float* W0 = (const float*)d_in[2];  const float* bb0 = (const float*)d_in[3];
    const float* Wb1 = (const float*)d_in[4]; const float* bb1 = (const float*)d_in[5];
    const float* W2 = (const float*)d_in[6];  const float* bb2 = (const float*)d_in[7];
    const float* W3 = (const float*)d_in[8];  const float* bb3 = (const float*)d_in[9];
    const float* W1m = (const float*)d_in[10]; const float* b1m = (const float*)d_in[11];
    const float* W2m = (const float*)d_in[12]; const float* b2m = (const float*)d_in[13];
    const float* W3m = (const float*)d_in[14]; const float* b3m = (const float*)d_in[15];
    const float* W4m = (const float*)d_in[16]; const float* b4m = (const float*)d_in[17];
    float* out = (float*)d_out;

    const int nState = 4 * Bn * Hn;
    zero_hc<<<(nState + 255) / 256, 256>>>();

    dim3 sgrid(G4 / 128, Bn / 128, 4);   // 16 x 2 x 4 = 128 blocks
    for (int t = 0; t < Tn; t++) {
        lstm_step_gemm<<<sgrid, 256>>>(prem, hyp, W0, Wb1, W2, W3, bb0, bb1, bb2, bb3, t);
        lstm_update<<<(nState / 4 + 255) / 256, 256>>>();
    }

    build_rnn<<<(nState + 255) / 256, 256>>>();

    // a1 = tanh(rnn @ W1 + b1): M=256,N=1024,K=2048  (rnn -> bufA)
    mlp_gemm<<<dim3(1024 / 64, Bn / 64), 256>>>(0, W1m, b1m, 1, Bn, 1024, 2048, 1);
    // a2 = tanh(a1 @ W2 + b2)  (bufA -> bufB)
    mlp_gemm<<<dim3(1024 / 64, Bn / 64), 256>>>(1, W2m, b2m, 2, Bn, 1024, 1024, 1);
    // a3 = tanh(a2 @ W3 + b3)  (bufB -> bufA)
    mlp_gemm<<<dim3(1024 / 64, Bn / 64), 256>>>(2, W3m, b3m, 1, Bn, 1024, 1024, 1);
    // logits = a3 @ W4 + b4
    final_gemm<<<Bn, 128>>>(W4m, b4m, out);
}

// round 6
// speedup vs baseline: 1.3955x; 1.3955x over previous
#include <cuda_runtime.h>
#include <cuda_bf16.h>
#include <stdint.h>
#include <math.h>

#define Bn 256
#define Tn 128
#define En 300
#define Hn 512
#define G4 2048

// ---------------- static device scratch ----------------
__device__ float g_xproj[(size_t)4 * Tn * Bn * G4];        // [l][t][b][n'] (includes bias) ~1GB
__device__ __nv_bfloat16 g_Wxh[4 * 320 * G4];              // x-weights, padded K=320, permuted cols
__device__ __nv_bfloat16 g_Wxl[4 * 320 * G4];
__device__ __nv_bfloat16 g_Whh[4 * Hn * G4];               // h-weights, permuted cols
__device__ __nv_bfloat16 g_Whl[4 * Hn * G4];
__device__ __nv_bfloat16 g_hh[2][4 * Bn * Hn];             // h hi, double buffered
__device__ __nv_bfloat16 g_hl[2][4 * Bn * Hn];             // h lo
__device__ float g_c[4 * Bn * Hn];
__device__ float g_bias_p[4 * G4];
__device__ float g_rnn[Bn * G4];
__device__ float g_bufA[Bn * 1024];
__device__ float g_bufB[Bn * 1024];
__device__ unsigned g_bar_cnt;
__device__ unsigned g_bar_gen;

__device__ __forceinline__ float sigf(float x) { return 1.f / (1.f + expf(-x)); }

__device__ __forceinline__ uint32_t s2u(const void* p) {
    uint32_t a;
    asm("{ .reg .u64 t; cvta.to.shared.u64 t, %1; cvt.u32.u64 %0, t; }" : "=r"(a) : "l"(p));
    return a;
}

// ---------------- smem tile loaders ----------------
// B tile: 32 K-rows x 128 N-cols from [K][2048] bf16 global, rows padded to 136
__device__ __forceinline__ void load_B(const __nv_bfloat16* __restrict__ src, int k0, int n0,
                                       __nv_bfloat16 (*bs)[136], int tid) {
#pragma unroll
    for (int it = 0; it < 2; it++) {
        int slot = it * 256 + tid;
        int row = slot >> 4, c16 = slot & 15;
        uint4 v = *(const uint4*)(src + (size_t)(k0 + row) * G4 + n0 + c16 * 8);
        *(uint4*)&bs[row][c16 * 8] = v;
    }
}
// A tile (recurrence): 128 rows x 32 K from h [row][512] bf16
__device__ __forceinline__ void load_Ah(const __nv_bfloat16* __restrict__ src, int k0,
                                        __nv_bfloat16 (*as)[40], int tid) {
#pragma unroll
    for (int it = 0; it < 2; it++) {
        int slot = it * 256 + tid;
        int row = slot >> 2, c16 = slot & 3;
        uint4 v = *(const uint4*)(src + (size_t)row * Hn + k0 + c16 * 8);
        *(uint4*)&as[row][c16 * 8] = v;
    }
}
// A tile (phase1): 128 t-rows x 32 K from x fp32 [row-stride 300], split hi/lo
__device__ __forceinline__ void load_Ax(const float* __restrict__ xrow0, int k0, int split_lo,
                                        __nv_bfloat16 (*as)[40], int tid) {
#pragma unroll
    for (int it = 0; it < 4; it++) {
        int slot = it * 256 + tid;
        int row = slot >> 3, f4 = slot & 7;
        int col = k0 + f4 * 4;
        float4 v = make_float4(0.f, 0.f, 0.f, 0.f);
        if (col <= En - 4) v = *(const float4*)(xrow0 + (size_t)row * En + col);
        float vv[4] = {v.x, v.y, v.z, v.w};
        unsigned short r[4];
#pragma unroll
        for (int q = 0; q < 4; q++) {
            __nv_bfloat16 h = __float2bfloat16(vv[q]);
            __nv_bfloat16 o = split_lo ? __float2bfloat16(vv[q] - __bfloat162float(h)) : h;
            r[q] = __bfloat16_as_ushort(o);
        }
        uint2 pk;
        pk.x = (uint32_t)r[0] | ((uint32_t)r[1] << 16);
        pk.y = (uint32_t)r[2] | ((uint32_t)r[3] << 16);
        *(uint2*)&as[row][f4 * 4] = pk;
    }
}

// ---------------- warp MMA over one K=32 chunk ----------------
// warp grid 2(M)x4(N): warp tile 64x32. A frag via ldmatrix.x4, B via ldmatrix.x2.trans.
__device__ __forceinline__ void mma_chunk(uint32_t abase, uint32_t bbase, int wm, int wn, int lane,
                                          float (*c)[4][4]) {
#pragma unroll
    for (int ks = 0; ks < 2; ks++) {
        const int k0 = ks * 16;
        uint32_t a[4][4], bfr[4][2];
        const int rlo = (lane & 7) + ((lane >> 3) & 1) * 8;
        const int cc = k0 + ((lane >> 4) & 1) * 8;
#pragma unroll
        for (int mi = 0; mi < 4; mi++) {
            uint32_t addr = abase + (uint32_t)(((wm * 64 + mi * 16 + rlo) * 40 + cc) * 2);
            asm volatile("ldmatrix.sync.aligned.m8n8.x4.shared.b16 {%0,%1,%2,%3}, [%4];"
                         : "=r"(a[mi][0]), "=r"(a[mi][1]), "=r"(a[mi][2]), "=r"(a[mi][3])
                         : "r"(addr));
        }
        const int brow = k0 + (lane & 15);
#pragma unroll
        for (int ni = 0; ni < 4; ni++) {
            uint32_t addr = bbase + (uint32_t)((brow * 136 + wn * 32 + ni * 8) * 2);
            asm volatile("ldmatrix.sync.aligned.m8n8.x2.trans.shared.b16 {%0,%1}, [%2];"
                         : "=r"(bfr[ni][0]), "=r"(bfr[ni][1]) : "r"(addr));
        }
#pragma unroll
        for (int mi = 0; mi < 4; mi++)
#pragma unroll
            for (int ni = 0; ni < 4; ni++)
                asm volatile("mma.sync.aligned.m16n8k16.row.col.f32.bf16.bf16.f32 "
                             "{%0,%1,%2,%3}, {%4,%5,%6,%7}, {%8,%9}, {%0,%1,%2,%3};"
                             : "+f"(c[mi][ni][0]), "+f"(c[mi][ni][1]),
                               "+f"(c[mi][ni][2]), "+f"(c[mi][ni][3])
                             : "r"(a[mi][0]), "r"(a[mi][1]), "r"(a[mi][2]), "r"(a[mi][3]),
                               "r"(bfr[ni][0]), "r"(bfr[ni][1]));
    }
}

// ---------------- prep: split + transpose-permute weights ----------------
// permuted col: n' = (n % 512)*4 + (n/512)  -> gates interleaved per hidden unit
__global__ void prep_w(const float* __restrict__ W0, const float* __restrict__ W1,
                       const float* __restrict__ W2, const float* __restrict__ W3) {
    int idx = blockIdx.x * blockDim.x + threadIdx.x;
    if (idx >= 4 * 812 * G4) return;
    int l = idx / (812 * G4);
    int rem = idx - l * (812 * G4);
    int k = rem / G4, n = rem - (rem / G4) * G4;
    const float* W = (l == 0) ? W0 : (l == 1) ? W1 : (l == 2) ? W2 : W3;
    float w = W[rem];
    int np = (n & 511) * 4 + (n >> 9);
    __nv_bfloat16 hi = __float2bfloat16(w);
    __nv_bfloat16 lo = __float2bfloat16(w - __bfloat162float(hi));
    if (k < En) {
        size_t o = ((size_t)l * 320 + k) * G4 + np;
        g_Wxh[o] = hi; g_Wxl[o] = lo;
    } else {
        size_t o = ((size_t)l * Hn + (k - En)) * G4 + np;
        g_Whh[o] = hi; g_Whl[o] = lo;
    }
}

__global__ void prep_bias_zero(const float* __restrict__ b0, const float* __restrict__ b1,
                               const float* __restrict__ b2, const float* __restrict__ b3) {
    int idx = blockIdx.x * blockDim.x + threadIdx.x;
    if (idx < 4 * G4) {
        int l = idx >> 11, n = idx & 2047;
        const float* b = (l == 0) ? b0 : (l == 1) ? b1 : (l == 2) ? b2 : b3;
        g_bias_p[l * G4 + ((n & 511) * 4 + (n >> 9))] = b[n];
    }
    if (idx < 4 * Bn * Hn) {
        g_c[idx] = 0.f;
        g_hh[0][idx] = __float2bfloat16(0.f);
        g_hl[0][idx] = __float2bfloat16(0.f);
    }
}

// ---------------- phase 1: xproj[l][t][b][n'] = x @ Wx' + b'  (3-pass split) ----------------
__global__ __launch_bounds__(256, 1) void xproj_gemm(const float* __restrict__ prem,
                                                     const float* __restrict__ hyp) {
    __shared__ __align__(16) __nv_bfloat16 As[2][128][40];
    __shared__ __align__(16) __nv_bfloat16 Bs[2][32][136];
    const int nt = blockIdx.x, b = blockIdx.y, l = blockIdx.z;
    const int n0 = nt * 128;
    const float* X = (l < 2) ? prem : hyp;
    const float* xrow = X + (size_t)b * Tn * En;
    const __nv_bfloat16* Wh_ = g_Wxh + (size_t)l * 320 * G4;
    const __nv_bfloat16* Wl_ = g_Wxl + (size_t)l * 320 * G4;
    const int tid = threadIdx.x, lane = tid & 31, w = tid >> 5;
    const int wm = w >> 2, wn = w & 3;

    float c[4][4][4];
#pragma unroll
    for (int i = 0; i < 4; i++)
#pragma unroll
        for (int j = 0; j < 4; j++)
#pragma unroll
            for (int q = 0; q < 4; q++) c[i][j][q] = 0.f;

    for (int p = 0; p < 3; p++) {
        const __nv_bfloat16* Bsrc = (p == 1) ? Wl_ : Wh_;
        const int alo = (p == 2);
        load_Ax(xrow, 0, alo, As[0], tid);
        load_B(Bsrc, 0, n0, Bs[0], tid);
        __syncthreads();
        for (int ch = 0; ch < 10; ch++) {
            int buf = ch & 1;
            if (ch + 1 < 10) {
                load_Ax(xrow, (ch + 1) * 32, alo, As[buf ^ 1], tid);
                load_B(Bsrc, (ch + 1) * 32, n0, Bs[buf ^ 1], tid);
            }
            mma_chunk(s2u(&As[buf][0][0]), s2u(&Bs[buf][0][0]), wm, wn, lane, c);
            __syncthreads();
        }
    }
    const float* bp = g_bias_p + l * G4;
    float* outl = g_xproj + (size_t)l * Tn * Bn * G4;
#pragma unroll
    for (int mi = 0; mi < 4; mi++) {
        int t = wm * 64 + mi * 16 + (lane >> 2);
#pragma unroll
        for (int ni = 0; ni < 4; ni++) {
            int col = n0 + wn * 32 + ni * 8 + (lane & 3) * 2;
            float2 v0 = {c[mi][ni][0] + bp[col], c[mi][ni][1] + bp[col + 1]};
            float2 v1 = {c[mi][ni][2] + bp[col], c[mi][ni][3] + bp[col + 1]};
            *(float2*)&outl[((size_t)t * Bn + b) * G4 + col] = v0;
            *(float2*)&outl[((size_t)(t + 8) * Bn + b) * G4 + col] = v1;
        }
    }
}

// ---------------- grid barrier (128 co-resident CTAs) ----------------
__device__ __forceinline__ void grid_sync() {
    __syncthreads();
    if (threadIdx.x == 0) {
        __threadfence();
        unsigned gen = atomicAdd(&g_bar_gen, 0u);
        unsigned a = atomicAdd(&g_bar_cnt, 1u);
        if (a == 127u) {
            atomicExch(&g_bar_cnt, 0u);
            __threadfence();
            atomicAdd(&g_bar_gen, 1u);
        } else {
            while (atomicAdd(&g_bar_gen, 0u) == gen) __nanosleep(64);
            __threadfence();
        }
    }
    __syncthreads();
}

// ---------------- persistent recurrence: 128 steps, fused update in epilogue ----------------
__global__ __launch_bounds__(256, 1) void lstm_persist() {
    __shared__ __align__(16) __nv_bfloat16 As[2][128][40];
    __shared__ __align__(16) __nv_bfloat16 Bs[2][32][136];
    const int bid = blockIdx.x;
    const int l = bid >> 5, mt = (bid >> 4) & 1, nt = bid & 15;
    const int m0 = mt * 128, n0 = nt * 128;
    const __nv_bfloat16* Whh_ = g_Whh + (size_t)l * Hn * G4;
    const __nv_bfloat16* Whl_ = g_Whl + (size_t)l * Hn * G4;
    const float* xp = g_xproj + (size_t)l * Tn * Bn * G4;
    const int tid = threadIdx.x, lane = tid & 31, w = tid >> 5;
    const int wm = w >> 2, wn = w & 3;
    const bool evn = !(lane & 1);

    for (int t = 0; t < Tn; t++) {
        const int rb = t & 1, wb = rb ^ 1;
        const int tt = (l & 1) ? (Tn - 1 - t) : t;

        float c[4][4][4];
#pragma unroll
        for (int mi = 0; mi < 4; mi++) {
            int bl = m0 + wm * 64 + mi * 16 + (lane >> 2);
#pragma unroll
            for (int ni = 0; ni < 4; ni++) {
                int col = n0 + wn * 32 + ni * 8 + (lane & 3) * 2;
                float2 v0 = *(const float2*)&xp[((size_t)tt * Bn + bl) * G4 + col];
                float2 v1 = *(const float2*)&xp[((size_t)tt * Bn + bl + 8) * G4 + col];
                c[mi][ni][0] = v0.x; c[mi][ni][1] = v0.y;
                c[mi][ni][2] = v1.x; c[mi][ni][3] = v1.y;
            }
        }

        for (int p = 0; p < 3; p++) {
            const __nv_bfloat16* Asrc = ((p == 2) ? g_hl[rb] : g_hh[rb]) + ((size_t)l * Bn + m0) * Hn;
            const __nv_bfloat16* Bsrc = (p == 1) ? Whl_ : Whh_;
            load_Ah(Asrc, 0, As[0], tid);
            load_B(Bsrc, 0, n0, Bs[0], tid);
            __syncthreads();
            for (int ch = 0; ch < 16; ch++) {
                int buf = ch & 1;
                if (ch + 1 < 16) {
                    load_Ah(Asrc, (ch + 1) * 32, As[buf ^ 1], tid);
                    load_B(Bsrc, (ch + 1) * 32, n0, Bs[buf ^ 1], tid);
                }
                mma_chunk(s2u(&As[buf][0][0]), s2u(&Bs[buf][0][0]), wm, wn, lane, c);
                __syncthreads();
            }
        }

        // fused LSTM update: lane pairs exchange (i,j)<->(f,o); even lane row r, odd r+8
#pragma unroll
        for (int mi = 0; mi < 4; mi++) {
            int bl = m0 + wm * 64 + mi * 16 + (lane >> 2) + (evn ? 0 : 8);
#pragma unroll
            for (int ni = 0; ni < 4; ni++) {
                float x0 = c[mi][ni][0], x1 = c[mi][ni][1];
                float x2 = c[mi][ni][2], x3 = c[mi][ni][3];
                float y0 = __shfl_xor_sync(0xffffffffu, x0, 1);
                float y1 = __shfl_xor_sync(0xffffffffu, x1, 1);
                float y2 = __shfl_xor_sync(0xffffffffu, x2, 1);
                float y3 = __shfl_xor_sync(0xffffffffu, x3, 1);
                float gi = evn ? x0 : y2;
                float gj = evn ? x1 : y3;
                float gf = evn ? y0 : x2;
                float go = evn ? y1 : x3;
                int u = nt * 32 + wn * 8 + ni * 2 + ((lane & 3) >> 1);
                size_t ci = ((size_t)l * Bn + bl) * Hn + u;
                float cc = g_c[ci];
                float cn = cc * sigf(gf + 1.f) + sigf(gi) * tanhf(gj);
                g_c[ci] = cn;
                float hv = tanhf(cn) * sigf(go);
                __nv_bfloat16 hh = __float2bfloat16(hv);
                g_hh[wb][ci] = hh;
                g_hl[wb][ci] = __float2bfloat16(hv - __bfloat162float(hh));
            }
        }
        grid_sync();
    }
}

// ---------------- tail: rnn concat + MLP ----------------
__global__ void build_rnn() {
    int idx = blockIdx.x * blockDim.x + threadIdx.x;
    if (idx >= 4 * Bn * Hn) return;
    int l = idx / (Bn * Hn);
    int r = idx - l * (Bn * Hn);
    int b = r / Hn, j = r - b * Hn;
    g_rnn[b * G4 + l * Hn + j] = g_c[idx];
}

__global__ __launch_bounds__(256) void mlp_gemm(
    int asel, const float* __restrict__ W, const float* __restrict__ bias,
    int csel, int N, int K, int act) {
    const float* __restrict__ A = (asel == 0) ? g_rnn : (asel == 1) ? g_bufA : g_bufB;
    float* __restrict__ C = (csel == 1) ? g_bufA : g_bufB;
    __shared__ __align__(16) float As[16][68];
    __shared__ __align__(16) float Ws[16][68];
    int tid = threadIdx.x, tx = tid & 15, ty = tid >> 4;
    int row0 = blockIdx.y * 64, col0 = blockIdx.x * 64;
    float acc[4][4] = {};
    for (int k0 = 0; k0 < K; k0 += 16) {
#pragma unroll
        for (int it = 0; it < 4; it++) {
            int idx = it * 256 + tid;
            int kk = idx & 15, ar = idx >> 4;
            As[kk][ar] = A[(size_t)(row0 + ar) * K + k0 + kk];
            int wc = idx & 63, wk = idx >> 6;
            Ws[wk][wc] = W[(size_t)(k0 + wk) * N + col0 + wc];
        }
        __syncthreads();
#pragma unroll
        for (int kk = 0; kk < 16; kk++) {
            float4 ra = *(const float4*)&As[kk][ty * 4];
            float4 rw = *(const float4*)&Ws[kk][tx * 4];
            float a[4] = {ra.x, ra.y, ra.z, ra.w};
            float wv[4] = {rw.x, rw.y, rw.z, rw.w};
#pragma unroll
            for (int i = 0; i < 4; i++)
#pragma unroll
                for (int j = 0; j < 4; j++) acc[i][j] += a[i] * wv[j];
        }
        __syncthreads();
    }
#pragma unroll
    for (int i = 0; i < 4; i++) {
        int row = row0 + ty * 4 + i;
#pragma unroll
        for (int j = 0; j < 4; j++) {
            int col = col0 + tx * 4 + j;
            float v = acc[i][j] + bias[col];
            if (act) v = tanhf(v);
            C[(size_t)row * N + col] = v;
        }
    }
}

__global__ void final_gemm(const float* __restrict__ W4, const float* __restrict__ b4,
                           float* __restrict__ out) {
    int b = blockIdx.x;
    int tid = threadIdx.x;   // 128
    float s0 = 0.f, s1 = 0.f, s2 = 0.f;
    const float* __restrict__ A = g_bufA + (size_t)b * 1024;
    for (int k = tid; k < 1024; k += 128) {
        float a = A[k];
        s0 += a * W4[k * 3 + 0];
        s1 += a * W4[k * 3 + 1];
        s2 += a * W4[k * 3 + 2];
    }
    for (int off = 16; off > 0; off >>= 1) {
        s0 += __shfl_down_sync(0xffffffffu, s0, off);
        s1 += __shfl_down_sync(0xffffffffu, s1, off);
        s2 += __shfl_down_sync(0xffffffffu, s2, off);
    }
    __shared__ float sh[3][4];
    int w = tid >> 5;
    if ((tid & 31) == 0) { sh[0][w] = s0; sh[1][w] = s1; sh[2][w] = s2; }
    __syncthreads();
    if (tid < 3) out[b * 3 + tid] = sh[tid][0] + sh[tid][1] + sh[tid][2] + sh[tid][3] + b4[tid];
}

// =====================================================================
extern "C" void kernel_launch(void* const* d_in, const int* in_sizes, int n_in,
                              void* d_out, int out_size) {
    const float* prem = (const float*)d_in[0];
    const float* hyp  = (const float*)d_in[1];
    const float* W0  = (const float*)d_in[2];  const float* bb0 = (const float*)d_in[3];
    const float* Wb1 = (const float*)d_in[4];  const float* bb1 = (const float*)d_in[5];
    const float* W2  = (const float*)d_in[6];  const float* bb2 = (const float*)d_in[7];
    const float* W3  = (const float*)d_in[8];  const float* bb3 = (const float*)d_in[9];
    const float* W1m = (const float*)d_in[10]; const float* b1m = (const float*)d_in[11];
    const float* W2m = (const float*)d_in[12]; const float* b2m = (const float*)d_in[13];
    const float* W3m = (const float*)d_in[14]; const float* b3m = (const float*)d_in[15];
    const float* W4m = (const float*)d_in[16]; const float* b4m = (const float*)d_in[17];
    float* out = (float*)d_out;

    prep_w<<<(4 * 812 * G4 + 255) / 256, 256>>>(W0, Wb1, W2, W3);
    prep_bias_zero<<<(4 * Bn * Hn + 255) / 256, 256>>>(bb0, bb1, bb2, bb3);

    xproj_gemm<<<dim3(16, Bn, 4), 256>>>(prem, hyp);

    lstm_persist<<<128, 256>>>();

    build_rnn<<<(4 * Bn * Hn + 255) / 256, 256>>>();
    mlp_gemm<<<dim3(1024 / 64, Bn / 64), 256>>>(0, W1m, b1m, 1, 1024, 2048, 1);
    mlp_gemm<<<dim3(1024 / 64, Bn / 64), 256>>>(1, W2m, b2m, 2, 1024, 1024, 1);
    mlp_gemm<<<dim3(1024 / 64, Bn / 64), 256>>>(2, W3m, b3m, 1, 1024, 1024, 1);
    final_gemm<<<Bn, 128>>>(W4m, b4m, out);
}